// round 15
// baseline (speedup 1.0000x reference)
#include <cuda_runtime.h>
#include <cuda_fp16.h>
#include <cstdint>
#include <cstddef>

// ---------------- dims ----------------
#define BATCH   256
#define SEQ     512
#define EMBD    100
#define HID     1024
#define THREADS 256

// setup work-item counts
#define NX (SEQ*4*2*4*4*32*4)     // 8388608  X-image u32s
#define NW (18*32*4*4*2*32*4)     // 2359296  W-image u32s
#define NH (4*2*32*4*32*4)        // 131072   H-image u32s

// ---------------- device scratch (fragment-order images; identical to R13) ----------------
// B (weights): [kc18][n_t32][wn4][j4][pair2][lane32] uint4; gate = n8, h = n_t*32+wn*8+grp
__device__ uint4 d_Wb[(size_t)18*32*4*4*2*32];
// A (X):       [t512][m_t4][rb2][xk4][f4][lane32] uint4
__device__ uint4 d_Xa[(size_t)SEQ*4*2*4*4*32];
// A (H state): [buf2][m_t4][rb2][hk32][f4][lane32] uint4
__device__ uint4 d_Ha[2][(size_t)4*2*32*4*32];
__device__ float d_biasp[4096];     // [g][1024]
__device__ unsigned d_barc[4];      // per-m_t grid-barrier counters

// ---------------- helpers ----------------
__device__ __forceinline__ float sigf(float x){ return 1.0f/(1.0f + __expf(-x)); }
__device__ __forceinline__ unsigned packh2(float a, float b){
    __half2 h = __floats2half2_rn(a, b);
    return *reinterpret_cast<unsigned*>(&h);
}
__device__ __forceinline__ void mma16(float c[4], unsigned a0, unsigned a1, unsigned a2, unsigned a3,
                                      unsigned b0, unsigned b1){
    asm volatile("mma.sync.aligned.m16n8k16.row.col.f32.f16.f16.f32 "
        "{%0,%1,%2,%3}, {%4,%5,%6,%7}, {%8,%9}, {%0,%1,%2,%3};"
        : "+f"(c[0]), "+f"(c[1]), "+f"(c[2]), "+f"(c[3])
        : "r"(a0), "r"(a1), "r"(a2), "r"(a3), "r"(b0), "r"(b1));
}

// ---------------- fused setup kernel (identical layouts to R13) ----------------
__global__ void k_setup(const int* __restrict__ tokens, const float* __restrict__ emb,
                        const float* __restrict__ H0,
    const float* __restrict__ Wxi, const float* __restrict__ Whi,
    const float* __restrict__ Wxf, const float* __restrict__ Whf,
    const float* __restrict__ Wxo, const float* __restrict__ Who,
    const float* __restrict__ Wxc, const float* __restrict__ Whc,
    const float* __restrict__ bi, const float* __restrict__ bf,
    const float* __restrict__ bo, const float* __restrict__ bc)
{
    int id = blockIdx.x*blockDim.x + threadIdx.x;
    if (id < NX){
        int i = id;
        int c = i&3, l = (i>>2)&31, f = (i>>7)&3, xk = (i>>9)&3;
        int rb = (i>>11)&1, mt = (i>>12)&3, t = i>>14;
        int b = mt*64 + rb*32 + (f>>1)*16 + (c&1)*8 + (l>>2);
        int e = xk*32 + (f&1)*16 + ((c>>1)&1)*8 + (l&3)*2;
        float f0 = 0.0f, f1 = 0.0f;
        if (e < EMBD){
            int tok = tokens[b*SEQ + t];
            f0 = emb[(size_t)tok*EMBD + e];
            if (e + 1 < EMBD) f1 = emb[(size_t)tok*EMBD + e + 1];
        }
        reinterpret_cast<unsigned*>(d_Xa)[i] = packh2(f0, f1);
        return;
    }
    id -= NX;
    if (id < NW){
        int i = id;
        int c = i&3, lane = (i>>2)&31, pair = (i>>7)&1, j = (i>>8)&3;
        int wn = (i>>10)&3, n_t = (i>>12)&31, kc = i>>17;
        int n8 = pair*2 + (c>>1), khalf = c&1;
        int k = kc*64 + j*16 + khalf*8 + (lane&3)*2;
        int h = n_t*32 + wn*8 + (lane>>2);
        int g = n8;
        const float* Wh = (g==0)?Whi:(g==1)?Whf:(g==2)?Who:Whc;
        const float* Wx = (g==0)?Wxi:(g==1)?Wxf:(g==2)?Wxo:Wxc;
        float f0 = 0.0f, f1 = 0.0f;
        if (k < 1024)             f0 = Wh[(size_t)k*HID + h];
        else if (k < 1024+EMBD)   f0 = Wx[(size_t)(k-1024)*HID + h];
        int k1 = k + 1;
        if (k1 < 1024)            f1 = Wh[(size_t)k1*HID + h];
        else if (k1 < 1024+EMBD)  f1 = Wx[(size_t)(k1-1024)*HID + h];
        reinterpret_cast<unsigned*>(d_Wb)[i] = packh2(f0, f1);
        return;
    }
    id -= NW;
    if (id < NH){
        int i = id;
        int c = i&3, l = (i>>2)&31, f = (i>>7)&3, hk = (i>>9)&31;
        int rb = (i>>14)&1, mt = (i>>15)&3;
        int b = mt*64 + rb*32 + (f>>1)*16 + (c&1)*8 + (l>>2);
        int k = hk*32 + (f&1)*16 + ((c>>1)&1)*8 + (l&3)*2;
        reinterpret_cast<unsigned*>(d_Ha[0])[i] =
            packh2(H0[(size_t)b*HID + k], H0[(size_t)b*HID + k + 1]);
        return;
    }
    id -= NH;
    if (id < 4096){
        int g = id >> 10, h = id & 1023;
        d_biasp[id] = (g==0?bi:g==1?bf:g==2?bo:bc)[h];
    }
    if (id < 4) d_barc[id] = 0;
}

// ---------------- persistent split-K direct-LDG LSTM scan (8 warps, 64x32 warp tiles) ----------------
__global__ void __launch_bounds__(THREADS,1)
lstm_dg(const float* __restrict__ C0, const float* __restrict__ dw,
        const float* __restrict__ db, float* __restrict__ out)
{
    __shared__ float4 exbuf[2048];     // 32KB split-K exchange: [warp8][ml*4+g][lane]
    const int tid  = threadIdx.x;
    const int warp = tid >> 5, lane = tid & 31;
    const int kg   = warp >> 2;        // k-group 0/1 (K halves of 576)
    const int wn   = warp & 3;         // 32-col slice (8h x 4 gates)
    const int grp  = lane >> 2, quad = lane & 3;
    const int m_t  = blockIdx.x >> 5, n_t = blockIdx.x & 31;
    const int hc0  = kg*18;            // first half-chunk of this group

    // fragment-stream base pointers
    const uint4* Bb = d_Wb + (size_t)(n_t*4 + wn)*256 + lane;
    const uint4* A0 = d_Ha[0] + (size_t)(m_t*2)*4096 + lane;   // rb=0 base
    const uint4* A1 = d_Ha[1] + (size_t)(m_t*2)*4096 + lane;

    // epilogue constants (kept rows: mi in {2kg, 2kg+1})
    const int hg0 = n_t*32 + wn*8 + quad*2;
    float bfr[4][2];
    #pragma unroll
    for (int g = 0; g < 4; g++){
        bfr[g][0] = d_biasp[g*1024 + hg0];
        bfr[g][1] = d_biasp[g*1024 + hg0 + 1];
    }
    float Cst[2][2][2];                // [ml][r8][hh]
    #pragma unroll
    for (int ml = 0; ml < 2; ml++)
        #pragma unroll
        for (int r8 = 0; r8 < 2; r8++)
            #pragma unroll
            for (int hh = 0; hh < 2; hh++){
                int brow = m_t*64 + kg*32 + ml*16 + grp + r8*8;
                Cst[ml][r8][hh] = C0[(size_t)brow*HID + hg0 + hh];
            }
    // H-image write base per ml: u32 idx = ((((m_t*2+kg)*32 + n_t)*4 + f)*32 + l)*4 + c
    unsigned wb[2];
    #pragma unroll
    for (int ml = 0; ml < 2; ml++)
        wb[ml] = (unsigned)(((((m_t*2+kg)*32 + n_t)*4 + (ml*2 + (wn>>1)))*32
                            + (grp*4+quad))*4 + 2*(wn&1));

    float acc[4][4][4];   // [mi][gate][c]
    uint4 av[2][8], bv[2][4];

    for (int t = 0; t < SEQ; ++t){
        const uint4* Ah = (t & 1) ? A1 : A0;
        unsigned* Hn = reinterpret_cast<unsigned*>((t & 1) ? d_Ha[0] : d_Ha[1]);
        const uint4* Xb = d_Xa + ((size_t)(t*4 + m_t)*2)*512 + lane;

        #pragma unroll
        for (int mi = 0; mi < 4; mi++)
            #pragma unroll
            for (int g = 0; g < 4; g++)
                acc[mi][g][0] = acc[mi][g][1] = acc[mi][g][2] = acc[mi][g][3] = 0.0f;

        // first half-chunk operands
        {
            #pragma unroll
            for (int rb = 0; rb < 2; rb++){
                const uint4* ap = (hc0 < 32) ? (Ah + rb*4096 + hc0*128)
                                             : (Xb + rb*512 + (hc0-32)*128);
                av[0][rb*4+0] = ap[0];  av[0][rb*4+1] = ap[32];
                av[0][rb*4+2] = ap[64]; av[0][rb*4+3] = ap[96];
            }
            const uint4* bp = Bb + (size_t)(hc0>>1)*32768 + (hc0&1)*128;
            bv[0][0] = bp[0];  bv[0][1] = bp[32]; bv[0][2] = bp[64]; bv[0][3] = bp[96];
        }

        #pragma unroll 2
        for (int i = 0; i < 18; i++){
            int cb = i & 1, nb = cb ^ 1;
            int hn = hc0 + i + 1;
            if (i + 1 < 18){
                #pragma unroll
                for (int rb = 0; rb < 2; rb++){
                    const uint4* ap = (hn < 32) ? (Ah + rb*4096 + hn*128)
                                                 : (Xb + rb*512 + (hn-32)*128);
                    av[nb][rb*4+0] = ap[0];  av[nb][rb*4+1] = ap[32];
                    av[nb][rb*4+2] = ap[64]; av[nb][rb*4+3] = ap[96];
                }
                const uint4* bp = Bb + (size_t)(hn>>1)*32768 + (hn&1)*128;
                bv[nb][0] = bp[0];  bv[nb][1] = bp[32]; bv[nb][2] = bp[64]; bv[nb][3] = bp[96];
            }
            #pragma unroll
            for (int ki = 0; ki < 2; ki++){
                uint4 b0 = bv[cb][ki*2], b1 = bv[cb][ki*2+1];
                #pragma unroll
                for (int mi = 0; mi < 4; mi++){
                    uint4 a = av[cb][(mi>>1)*4 + (mi&1)*2 + ki];
                    mma16(acc[mi][0], a.x,a.y,a.z,a.w, b0.x, b0.y);
                    mma16(acc[mi][1], a.x,a.y,a.z,a.w, b0.z, b0.w);
                    mma16(acc[mi][2], a.x,a.y,a.z,a.w, b1.x, b1.y);
                    mma16(acc[mi][3], a.x,a.y,a.z,a.w, b1.z, b1.w);
                }
            }
        }

        // split-K exchange: send partner's kept rows (mi = 2(1-kg), 2(1-kg)+1)
        {
            float4* ms = &exbuf[(size_t)warp*256 + lane];
            #pragma unroll
            for (int ml = 0; ml < 2; ml++){
                int sm_ = 2*(1-kg) + ml;
                #pragma unroll
                for (int g = 0; g < 4; g++)
                    ms[(ml*4+g)*32] = make_float4(acc[sm_][g][0], acc[sm_][g][1],
                                                  acc[sm_][g][2], acc[sm_][g][3]);
            }
        }
        __syncthreads();
        {
            const float4* ps = &exbuf[(size_t)((1-kg)*4 + wn)*256 + lane];
            #pragma unroll
            for (int ml = 0; ml < 2; ml++){
                int km = 2*kg + ml;
                #pragma unroll
                for (int g = 0; g < 4; g++){
                    float4 p = ps[(ml*4+g)*32];
                    acc[km][g][0] += p.x; acc[km][g][1] += p.y;
                    acc[km][g][2] += p.z; acc[km][g][3] += p.w;
                }
            }
        }

        // cell math in registers; H (fp16 pair) into next step's frag image
        #pragma unroll
        for (int ml = 0; ml < 2; ml++){
            int km = 2*kg + ml;
            #pragma unroll
            for (int r8 = 0; r8 < 2; r8++){
                float Hv[2];
                #pragma unroll
                for (int hh = 0; hh < 2; hh++){
                    int c = r8*2 + hh;
                    float vi = acc[km][0][c] + bfr[0][hh];
                    float vf = acc[km][1][c] + bfr[1][hh];
                    float vo = acc[km][2][c] + bfr[2][hh];
                    float vc = acc[km][3][c] + bfr[3][hh];
                    float Cn = sigf(vf)*Cst[ml][r8][hh] + sigf(vi)*tanhf(vc);
                    Cst[ml][r8][hh] = Cn;
                    Hv[hh] = sigf(vo)*tanhf(Cn);
                }
                Hn[wb[ml] + r8] = packh2(Hv[0], Hv[1]);
            }
        }

        // grid barrier (per-m_t group of 32 CTAs)
        __threadfence();
        __syncthreads();
        if (tid == 0){
            atomicAdd(&d_barc[m_t], 1u);
            unsigned target = (unsigned)(t+1)*32u, v;
            do { asm volatile("ld.acquire.gpu.u32 %0, [%1];" : "=r"(v) : "l"(&d_barc[m_t])); }
            while (v < target);
        }
        __syncthreads();
    }

    // ---- dense head: out[256,2] = H_final @ dense_w + dense_b (t=511 wrote buf 0) ----
    if (n_t == 0 && tid < 128){
        int rl = tid >> 1, cx = tid & 1;
        const unsigned* Hf = reinterpret_cast<const unsigned*>(d_Ha[0]);
        float sum = db[cx];
        int rb = rl >> 5, r32 = rl & 31, mi = r32 >> 4, r16 = r32 & 15;
        int clo = r16 >> 3, lbase = (r16 & 7)*4;
        for (int h = 0; h < HID; h += 2){
            int hk = h >> 5, h5 = h & 31, ki = h5 >> 4, kk = h5 & 15;
            int chi = kk >> 3, qd = (kk & 7) >> 1;
            int c = clo + chi*2, l = lbase + qd, f = mi*2 + ki;
            unsigned off = (unsigned)(((((m_t*2+rb)*32 + hk)*4 + f)*32 + l)*4 + c);
            unsigned v = Hf[off];
            __half2 hv = *reinterpret_cast<__half2*>(&v);
            sum += __low2float(hv)*dw[h*2 + cx] + __high2float(hv)*dw[(h+1)*2 + cx];
        }
        out[(m_t*64 + rl)*2 + cx] = sum;
    }
}

// ---------------- launcher ----------------
extern "C" void kernel_launch(void* const* d_in, const int* in_sizes, int n_in,
                              void* d_out, int out_size)
{
    const int*   tokens = (const int*)  d_in[0];
    const float* H0     = (const float*)d_in[1];
    const float* C0v    = (const float*)d_in[2];
    const float* Wxi = (const float*)d_in[3],  *Whi = (const float*)d_in[4],  *bi = (const float*)d_in[5];
    const float* Wxf = (const float*)d_in[6],  *Whf = (const float*)d_in[7],  *bf = (const float*)d_in[8];
    const float* Wxo = (const float*)d_in[9],  *Who = (const float*)d_in[10], *bo = (const float*)d_in[11];
    const float* Wxc = (const float*)d_in[12], *Whc = (const float*)d_in[13], *bc = (const float*)d_in[14];
    const float* emb = (const float*)d_in[15];
    const float* dw  = (const float*)d_in[16];
    const float* db  = (const float*)d_in[17];
    float* out = (float*)d_out;

    int total = NX + NW + NH + 4096;
    k_setup<<<(total + 255)/256, 256>>>(tokens, emb, H0,
        Wxi, Whi, Wxf, Whf, Wxo, Who, Wxc, Whc, bi, bf, bo, bc);
    // 128 CTAs (4 m-groups x 32 n-tiles), 256 threads, 1 CTA/SM
    lstm_dg<<<128, THREADS>>>(C0v, dw, db, out);
}

// round 16
// speedup vs baseline: 2.7142x; 2.7142x over previous
#include <cuda_runtime.h>
#include <cuda_fp16.h>
#include <cstdint>
#include <cstddef>

// ---------------- dims ----------------
#define BATCH   256
#define SEQ     512
#define EMBD    100
#define HID     1024
#define THREADS 512
#define GST     34          // gate smem row stride (floats)
#define GGT     (64*GST)    // per-gate block (2176 floats)
#define GKG     (4*GGT)     // per-k-group block (8704 floats)
#define DSMEM   122880      // force 1 CTA/SM (gsm uses 69632B of it)

// setup work-item counts
#define NX (SEQ*4*2*4*4*32*4)     // 8388608  X-image u32s
#define NW (18*32*4*4*2*32*4)     // 2359296  W-image u32s
#define NH (4*2*32*4*32*4)        // 131072   H-image u32s

// ---------------- device scratch (fragment-order images; R11 layouts) ----------------
// B (weights): [kc18][n_t32][wn4][j4][pair2][lane32] uint4; gate = wn
__device__ uint4 d_Wb[(size_t)18*32*4*4*2*32];
// A (X):       [t512][m_t4][rb2][xk4][f4][lane32] uint4
__device__ uint4 d_Xa[(size_t)SEQ*4*2*4*4*32];
// A (H state): [buf2][m_t4][rb2][hk32][f4][lane32] uint4
__device__ uint4 d_Ha[2][(size_t)4*2*32*4*32];
__device__ float d_biasp[4096];       // [g][1024]
__device__ unsigned d_barc[4*32];     // per-m_t grid-barrier counters, 128B apart

// ---------------- helpers ----------------
__device__ __forceinline__ float sigf(float x){ return 1.0f/(1.0f + __expf(-x)); }
__device__ __forceinline__ unsigned packh2(float a, float b){
    __half2 h = __floats2half2_rn(a, b);
    return *reinterpret_cast<unsigned*>(&h);
}
__device__ __forceinline__ void mma16(float c[4], unsigned a0, unsigned a1, unsigned a2, unsigned a3,
                                      unsigned b0, unsigned b1){
    asm volatile("mma.sync.aligned.m16n8k16.row.col.f32.f16.f16.f32 "
        "{%0,%1,%2,%3}, {%4,%5,%6,%7}, {%8,%9}, {%0,%1,%2,%3};"
        : "+f"(c[0]), "+f"(c[1]), "+f"(c[2]), "+f"(c[3])
        : "r"(a0), "r"(a1), "r"(a2), "r"(a3), "r"(b0), "r"(b1));
}

// ---------------- fused setup kernel (R11 layouts, bit-identical) ----------------
__global__ void k_setup(const int* __restrict__ tokens, const float* __restrict__ emb,
                        const float* __restrict__ H0,
    const float* __restrict__ Wxi, const float* __restrict__ Whi,
    const float* __restrict__ Wxf, const float* __restrict__ Whf,
    const float* __restrict__ Wxo, const float* __restrict__ Who,
    const float* __restrict__ Wxc, const float* __restrict__ Whc,
    const float* __restrict__ bi, const float* __restrict__ bf,
    const float* __restrict__ bo, const float* __restrict__ bc)
{
    int id = blockIdx.x*blockDim.x + threadIdx.x;
    if (id < NX){
        // X embed -> A-frag image
        int i = id;
        int c = i&3, l = (i>>2)&31, f = (i>>7)&3, xk = (i>>9)&3;
        int rb = (i>>11)&1, mt = (i>>12)&3, t = i>>14;
        int b = mt*64 + rb*32 + (f>>1)*16 + (c&1)*8 + (l>>2);
        int e = xk*32 + (f&1)*16 + ((c>>1)&1)*8 + (l&3)*2;
        float f0 = 0.0f, f1 = 0.0f;
        if (e < EMBD){
            int tok = tokens[b*SEQ + t];
            f0 = emb[(size_t)tok*EMBD + e];
            if (e + 1 < EMBD) f1 = emb[(size_t)tok*EMBD + e + 1];
        }
        reinterpret_cast<unsigned*>(d_Xa)[i] = packh2(f0, f1);
        return;
    }
    id -= NX;
    if (id < NW){
        // weights -> B-frag image (gate = wn; h slice = n8)   [R11 mapping]
        int i = id;
        int c = i&3, lane = (i>>2)&31, pair = (i>>7)&1, j = (i>>8)&3;
        int wn = (i>>10)&3, n_t = (i>>12)&31, kc = i>>17;
        int n8 = pair*2 + (c>>1), khalf = c&1;
        int k = kc*64 + j*16 + khalf*8 + (lane&3)*2;
        int h = n_t*32 + n8*8 + (lane>>2);
        int g = wn;
        const float* Wh = (g==0)?Whi:(g==1)?Whf:(g==2)?Who:Whc;
        const float* Wx = (g==0)?Wxi:(g==1)?Wxf:(g==2)?Wxo:Wxc;
        float f0 = 0.0f, f1 = 0.0f;
        if (k < 1024)             f0 = Wh[(size_t)k*HID + h];
        else if (k < 1024+EMBD)   f0 = Wx[(size_t)(k-1024)*HID + h];
        int k1 = k + 1;
        if (k1 < 1024)            f1 = Wh[(size_t)k1*HID + h];
        else if (k1 < 1024+EMBD)  f1 = Wx[(size_t)(k1-1024)*HID + h];
        reinterpret_cast<unsigned*>(d_Wb)[i] = packh2(f0, f1);
        return;
    }
    id -= NW;
    if (id < NH){
        // H0 -> A-frag image (buf 0)
        int i = id;
        int c = i&3, l = (i>>2)&31, f = (i>>7)&3, hk = (i>>9)&31;
        int rb = (i>>14)&1, mt = (i>>15)&3;
        int b = mt*64 + rb*32 + (f>>1)*16 + (c&1)*8 + (l>>2);
        int k = hk*32 + (f&1)*16 + ((c>>1)&1)*8 + (l&3)*2;
        reinterpret_cast<unsigned*>(d_Ha[0])[i] =
            packh2(H0[(size_t)b*HID + k], H0[(size_t)b*HID + k + 1]);
        return;
    }
    id -= NH;
    if (id < 4096){
        int g = id >> 10, h = id & 1023;
        d_biasp[id] = (g==0?bi:g==1?bf:g==2?bo:bc)[h];
    }
    if (id < 128) d_barc[id] = 0;
}

// ---------------- persistent split-K direct-LDG LSTM scan (R11 config) ----------------
__global__ void __launch_bounds__(THREADS,1)
lstm_dg(const float* __restrict__ C0, const float* __restrict__ dw,
        const float* __restrict__ db, float* __restrict__ out)
{
    extern __shared__ float gsm[];     // [2 kg][4 gates][64 rows][GST]
    const int tid  = threadIdx.x;
    const int warp = tid >> 5, lane = tid & 31;
    const int kg   = warp >> 3;        // k-group 0/1 (K halves of 576)
    const int wg   = warp & 7;
    const int wm   = wg >> 2, wn = wg & 3;   // 2(M:32) x 4(N:32) within group
    const int grp  = lane >> 2, quad = lane & 3;
    const int m_t  = blockIdx.x >> 5, n_t = blockIdx.x & 31;
    const int hc0  = kg*18;            // first half-chunk of this group

    // fragment-stream base pointers
    const uint4* Bb = d_Wb + (size_t)(n_t*4 + wn)*256 + lane;
    const uint4* A0 = d_Ha[0] + (size_t)(m_t*2 + wm)*4096 + lane;
    const uint4* A1 = d_Ha[1] + (size_t)(m_t*2 + wm)*4096 + lane;

    // epilogue ownership: thread -> row b0l, h-pairs hb, hb+1
    const int b0l = tid >> 4, hp = tid & 15;
    const int hl  = hp*2;                    // h within 32-slice (even)
    const int hg  = n_t*32 + hl;             // global h
    unsigned woff[2];
    {
        int hk = hg >> 5;
        int kk = hl & 15, ki = hl >> 4, chi = kk >> 3, qd = (kk & 7) >> 1;
        #pragma unroll
        for (int it = 0; it < 2; it++){
            int b = b0l + it*32;
            int rb = b >> 5, r32 = b & 31, mi = r32 >> 4, r16 = r32 & 15;
            int c = (r16 >> 3) + chi*2;
            int l = (r16 & 7)*4 + qd;
            int f = mi*2 + ki;
            woff[it] = (unsigned)(((((m_t*2+rb)*32 + hk)*4 + f)*32 + l)*4 + c);
        }
    }
    float Cst[2][2];
    #pragma unroll
    for (int it = 0; it < 2; it++){
        int b = m_t*64 + b0l + it*32;
        Cst[it][0] = C0[(size_t)b*HID + hg];
        Cst[it][1] = C0[(size_t)b*HID + hg + 1];
    }

    float acc[2][4][4];   // [mi][n8][c]
    uint4 av[2][4], bv[2][4];

    // pre-load first B half-chunk (weights are t-independent)
    {
        const uint4* bp = Bb + (size_t)(hc0>>1)*32768 + (hc0&1)*128;
        bv[0][0] = bp[0];  bv[0][1] = bp[32]; bv[0][2] = bp[64]; bv[0][3] = bp[96];
    }

    for (int t = 0; t < SEQ; ++t){
        const uint4* Ah = (t & 1) ? A1 : A0;
        unsigned* Hn = reinterpret_cast<unsigned*>((t & 1) ? d_Ha[0] : d_Ha[1]);
        const uint4* Xb = d_Xa + ((size_t)((t*4 + m_t)*2 + wm))*512 + lane;

        #pragma unroll
        for (int mi = 0; mi < 2; mi++)
            #pragma unroll
            for (int n8 = 0; n8 < 4; n8++)
                acc[mi][n8][0] = acc[mi][n8][1] = acc[mi][n8][2] = acc[mi][n8][3] = 0.0f;

        // first A half-chunk (depends on H -> after barrier); bv[0] already loaded
        {
            const uint4* ap = (hc0 < 32) ? (Ah + hc0*128) : (Xb + (hc0-32)*128);
            av[0][0] = ap[0];  av[0][1] = ap[32]; av[0][2] = ap[64]; av[0][3] = ap[96];
        }

        #pragma unroll 2
        for (int i = 0; i < 18; i++){
            int cb = i & 1, nb = cb ^ 1;
            int hn = hc0 + i + 1;
            if (i + 1 < 18){
                const uint4* ap = (hn < 32) ? (Ah + hn*128) : (Xb + (hn-32)*128);
                av[nb][0] = ap[0];  av[nb][1] = ap[32]; av[nb][2] = ap[64]; av[nb][3] = ap[96];
                const uint4* bp = Bb + (size_t)(hn>>1)*32768 + (hn&1)*128;
                bv[nb][0] = bp[0];  bv[nb][1] = bp[32]; bv[nb][2] = bp[64]; bv[nb][3] = bp[96];
            }
            #pragma unroll
            for (int ki = 0; ki < 2; ki++){
                uint4 b0 = bv[cb][ki*2], b1 = bv[cb][ki*2+1];
                #pragma unroll
                for (int mi = 0; mi < 2; mi++){
                    uint4 a = av[cb][mi*2 + ki];
                    mma16(acc[mi][0], a.x,a.y,a.z,a.w, b0.x, b0.y);
                    mma16(acc[mi][1], a.x,a.y,a.z,a.w, b0.z, b0.w);
                    mma16(acc[mi][2], a.x,a.y,a.z,a.w, b1.x, b1.y);
                    mma16(acc[mi][3], a.x,a.y,a.z,a.w, b1.z, b1.w);
                }
            }
        }

        // stage partial gates: gsm[kg][gate wn][row][h_l]
        {
            float* gb = gsm + kg*GKG + wn*GGT;
            #pragma unroll
            for (int mi = 0; mi < 2; mi++){
                int r0 = wm*32 + mi*16 + grp;
                #pragma unroll
                for (int n8 = 0; n8 < 4; n8++){
                    int nl = n8*8 + quad*2;
                    *reinterpret_cast<float2*>(&gb[r0*GST + nl])
                        = make_float2(acc[mi][n8][0], acc[mi][n8][1]);
                    *reinterpret_cast<float2*>(&gb[(r0+8)*GST + nl])
                        = make_float2(acc[mi][n8][2], acc[mi][n8][3]);
                }
            }
        }
        __syncthreads();

        // cell update: sum the two K-halves + bias; H into next step's frag image
        {
            float bi0 = d_biasp[hg],        bi1 = d_biasp[hg+1];
            float bf0 = d_biasp[1024+hg],   bf1 = d_biasp[1024+hg+1];
            float bo0 = d_biasp[2048+hg],   bo1 = d_biasp[2048+hg+1];
            float bc0 = d_biasp[3072+hg],   bc1 = d_biasp[3072+hg+1];
            #pragma unroll
            for (int it = 0; it < 2; it++){
                int b = b0l + it*32;
                float2 gi0 = *reinterpret_cast<float2*>(&gsm[        b*GST + hl]);
                float2 gf0 = *reinterpret_cast<float2*>(&gsm[GGT   + b*GST + hl]);
                float2 go0 = *reinterpret_cast<float2*>(&gsm[2*GGT + b*GST + hl]);
                float2 gc0 = *reinterpret_cast<float2*>(&gsm[3*GGT + b*GST + hl]);
                float2 gi1 = *reinterpret_cast<float2*>(&gsm[GKG         + b*GST + hl]);
                float2 gf1 = *reinterpret_cast<float2*>(&gsm[GKG + GGT   + b*GST + hl]);
                float2 go1 = *reinterpret_cast<float2*>(&gsm[GKG + 2*GGT + b*GST + hl]);
                float2 gc1 = *reinterpret_cast<float2*>(&gsm[GKG + 3*GGT + b*GST + hl]);
                float vi0 = gi0.x + gi1.x + bi0, vi1 = gi0.y + gi1.y + bi1;
                float vf0 = gf0.x + gf1.x + bf0, vf1 = gf0.y + gf1.y + bf1;
                float vo0 = go0.x + go1.x + bo0, vo1 = go0.y + go1.y + bo1;
                float vc0 = gc0.x + gc1.x + bc0, vc1 = gc0.y + gc1.y + bc1;
                float Cn0 = sigf(vf0)*Cst[it][0] + sigf(vi0)*tanhf(vc0);
                float Cn1 = sigf(vf1)*Cst[it][1] + sigf(vi1)*tanhf(vc1);
                Cst[it][0] = Cn0; Cst[it][1] = Cn1;
                float Hv0 = sigf(vo0)*tanhf(Cn0);
                float Hv1 = sigf(vo1)*tanhf(Cn1);
                Hn[woff[it]] = packh2(Hv0, Hv1);
            }
        }

        // prefetch next step's first B half-chunk (H-independent) before barrier
        if (t + 1 < SEQ){
            const uint4* bp = Bb + (size_t)(hc0>>1)*32768 + (hc0&1)*128;
            bv[0][0] = bp[0];  bv[0][1] = bp[32]; bv[0][2] = bp[64]; bv[0][3] = bp[96];
        }

        // grid barrier (per-m_t group of 32 CTAs; padded counters)
        __threadfence();
        __syncthreads();
        if (tid == 0){
            atomicAdd(&d_barc[m_t*32], 1u);
            unsigned target = (unsigned)(t+1)*32u, v;
            do { asm volatile("ld.acquire.gpu.u32 %0, [%1];" : "=r"(v) : "l"(&d_barc[m_t*32])); }
            while (v < target);
        }
        __syncthreads();
    }

    // ---- dense head: out[256,2] = H_final @ dense_w + dense_b (t=511 wrote buf 0) ----
    if (n_t == 0 && tid < 128){
        int rl = tid >> 1, cx = tid & 1;
        const unsigned* Hf = reinterpret_cast<const unsigned*>(d_Ha[0]);
        float sum = db[cx];
        int rb = rl >> 5, r32 = rl & 31, mi = r32 >> 4, r16 = r32 & 15;
        int clo = r16 >> 3, lbase = (r16 & 7)*4;
        for (int h = 0; h < HID; h += 2){
            int hk = h >> 5, h5 = h & 31, ki = h5 >> 4, kk = h5 & 15;
            int chi = kk >> 3, qd = (kk & 7) >> 1;
            int c = clo + chi*2, l = lbase + qd, f = mi*2 + ki;
            unsigned off = (unsigned)(((((m_t*2+rb)*32 + hk)*4 + f)*32 + l)*4 + c);
            unsigned v = Hf[off];
            __half2 hv = *reinterpret_cast<__half2*>(&v);
            sum += __low2float(hv)*dw[h*2 + cx] + __high2float(hv)*dw[(h+1)*2 + cx];
        }
        out[(m_t*64 + rl)*2 + cx] = sum;
    }
}

// ---------------- launcher ----------------
extern "C" void kernel_launch(void* const* d_in, const int* in_sizes, int n_in,
                              void* d_out, int out_size)
{
    const int*   tokens = (const int*)  d_in[0];
    const float* H0     = (const float*)d_in[1];
    const float* C0v    = (const float*)d_in[2];
    const float* Wxi = (const float*)d_in[3],  *Whi = (const float*)d_in[4],  *bi = (const float*)d_in[5];
    const float* Wxf = (const float*)d_in[6],  *Whf = (const float*)d_in[7],  *bf = (const float*)d_in[8];
    const float* Wxo = (const float*)d_in[9],  *Who = (const float*)d_in[10], *bo = (const float*)d_in[11];
    const float* Wxc = (const float*)d_in[12], *Whc = (const float*)d_in[13], *bc = (const float*)d_in[14];
    const float* emb = (const float*)d_in[15];
    const float* dw  = (const float*)d_in[16];
    const float* db  = (const float*)d_in[17];
    float* out = (float*)d_out;

    cudaFuncSetAttribute(lstm_dg, cudaFuncAttributeMaxDynamicSharedMemorySize, DSMEM);

    int total = NX + NW + NH + 4096;
    k_setup<<<(total + 255)/256, 256>>>(tokens, emb, H0,
        Wxi, Whi, Wxf, Whf, Wxo, Who, Wxc, Whc, bi, bf, bo, bc);
    // 128 CTAs (4 m-groups x 32 n-tiles), 512 threads, 1 CTA/SM
    lstm_dg<<<128, THREADS, DSMEM>>>(C0v, dw, db, out);
}

// round 17
// speedup vs baseline: 2.7156x; 1.0005x over previous
#include <cuda_runtime.h>
#include <cuda_fp16.h>
#include <cstdint>
#include <cstddef>

// ---------------- dims ----------------
#define BATCH   256
#define SEQ     512
#define EMBD    100
#define HID     1024
#define THREADS 512
#define GST     34          // gate smem row stride (floats)
#define GGT     (64*GST)    // per-gate block (2176 floats)
#define GKG     (4*GGT)     // per-k-group block (8704 floats)
#define DSMEM   122880      // force 1 CTA/SM (gsm uses 69632B of it)

// setup work-item counts
#define NX (SEQ*4*2*4*4*32*4)     // 8388608  X-image u32s
#define NW (18*32*4*4*2*32*4)     // 2359296  W-image u32s
#define NH (4*2*32*4*32*4)        // 131072   H-image u32s

// ---------------- device scratch (fragment-order images; R11 layouts) ----------------
// B (weights): [kc18][n_t32][wn4][j4][pair2][lane32] uint4; gate = wn
__device__ uint4 d_Wb[(size_t)18*32*4*4*2*32];
// A (X):       [t512][m_t4][rb2][xk4][f4][lane32] uint4
__device__ uint4 d_Xa[(size_t)SEQ*4*2*4*4*32];
// A (H state): [buf2][m_t4][rb2][hk32][f4][lane32] uint4
__device__ uint4 d_Ha[2][(size_t)4*2*32*4*32];
__device__ float d_biasp[4096];       // [g][1024]
__device__ unsigned d_barc[4*32];     // per-m_t grid-barrier counters, 128B apart

// ---------------- helpers ----------------
__device__ __forceinline__ float sigf(float x){ return 1.0f/(1.0f + __expf(-x)); }
__device__ __forceinline__ unsigned packh2(float a, float b){
    __half2 h = __floats2half2_rn(a, b);
    return *reinterpret_cast<unsigned*>(&h);
}
__device__ __forceinline__ void mma16(float c[4], unsigned a0, unsigned a1, unsigned a2, unsigned a3,
                                      unsigned b0, unsigned b1){
    asm volatile("mma.sync.aligned.m16n8k16.row.col.f32.f16.f16.f32 "
        "{%0,%1,%2,%3}, {%4,%5,%6,%7}, {%8,%9}, {%0,%1,%2,%3};"
        : "+f"(c[0]), "+f"(c[1]), "+f"(c[2]), "+f"(c[3])
        : "r"(a0), "r"(a1), "r"(a2), "r"(a3), "r"(b0), "r"(b1));
}

// ---------------- fused setup kernel (R11 layouts, bit-identical) ----------------
__global__ void k_setup(const int* __restrict__ tokens, const float* __restrict__ emb,
                        const float* __restrict__ H0,
    const float* __restrict__ Wxi, const float* __restrict__ Whi,
    const float* __restrict__ Wxf, const float* __restrict__ Whf,
    const float* __restrict__ Wxo, const float* __restrict__ Who,
    const float* __restrict__ Wxc, const float* __restrict__ Whc,
    const float* __restrict__ bi, const float* __restrict__ bf,
    const float* __restrict__ bo, const float* __restrict__ bc)
{
    int id = blockIdx.x*blockDim.x + threadIdx.x;
    if (id < NX){
        // X embed -> A-frag image
        int i = id;
        int c = i&3, l = (i>>2)&31, f = (i>>7)&3, xk = (i>>9)&3;
        int rb = (i>>11)&1, mt = (i>>12)&3, t = i>>14;
        int b = mt*64 + rb*32 + (f>>1)*16 + (c&1)*8 + (l>>2);
        int e = xk*32 + (f&1)*16 + ((c>>1)&1)*8 + (l&3)*2;
        float f0 = 0.0f, f1 = 0.0f;
        if (e < EMBD){
            int tok = tokens[b*SEQ + t];
            f0 = emb[(size_t)tok*EMBD + e];
            if (e + 1 < EMBD) f1 = emb[(size_t)tok*EMBD + e + 1];
        }
        reinterpret_cast<unsigned*>(d_Xa)[i] = packh2(f0, f1);
        return;
    }
    id -= NX;
    if (id < NW){
        // weights -> B-frag image (gate = wn; h slice = n8)   [R11 mapping]
        int i = id;
        int c = i&3, lane = (i>>2)&31, pair = (i>>7)&1, j = (i>>8)&3;
        int wn = (i>>10)&3, n_t = (i>>12)&31, kc = i>>17;
        int n8 = pair*2 + (c>>1), khalf = c&1;
        int k = kc*64 + j*16 + khalf*8 + (lane&3)*2;
        int h = n_t*32 + n8*8 + (lane>>2);
        int g = wn;
        const float* Wh = (g==0)?Whi:(g==1)?Whf:(g==2)?Who:Whc;
        const float* Wx = (g==0)?Wxi:(g==1)?Wxf:(g==2)?Wxo:Wxc;
        float f0 = 0.0f, f1 = 0.0f;
        if (k < 1024)             f0 = Wh[(size_t)k*HID + h];
        else if (k < 1024+EMBD)   f0 = Wx[(size_t)(k-1024)*HID + h];
        int k1 = k + 1;
        if (k1 < 1024)            f1 = Wh[(size_t)k1*HID + h];
        else if (k1 < 1024+EMBD)  f1 = Wx[(size_t)(k1-1024)*HID + h];
        reinterpret_cast<unsigned*>(d_Wb)[i] = packh2(f0, f1);
        return;
    }
    id -= NW;
    if (id < NH){
        // H0 -> A-frag image (buf 0)
        int i = id;
        int c = i&3, l = (i>>2)&31, f = (i>>7)&3, hk = (i>>9)&31;
        int rb = (i>>14)&1, mt = (i>>15)&3;
        int b = mt*64 + rb*32 + (f>>1)*16 + (c&1)*8 + (l>>2);
        int k = hk*32 + (f&1)*16 + ((c>>1)&1)*8 + (l&3)*2;
        reinterpret_cast<unsigned*>(d_Ha[0])[i] =
            packh2(H0[(size_t)b*HID + k], H0[(size_t)b*HID + k + 1]);
        return;
    }
    id -= NH;
    if (id < 4096){
        int g = id >> 10, h = id & 1023;
        d_biasp[id] = (g==0?bi:g==1?bf:g==2?bo:bc)[h];
    }
    if (id < 128) d_barc[id] = 0;
}

// ---------------- persistent split-K direct-LDG LSTM scan (R11 config) ----------------
__global__ void __launch_bounds__(THREADS,1)
lstm_dg(const float* __restrict__ C0, const float* __restrict__ dw,
        const float* __restrict__ db, float* __restrict__ out)
{
    extern __shared__ float gsm[];     // [2 kg][4 gates][64 rows][GST]
    const int tid  = threadIdx.x;
    const int warp = tid >> 5, lane = tid & 31;
    const int kg   = warp >> 3;        // k-group 0/1 (K halves of 576)
    const int wg   = warp & 7;
    const int wm   = wg >> 2, wn = wg & 3;   // 2(M:32) x 4(N:32) within group
    const int grp  = lane >> 2, quad = lane & 3;
    const int m_t  = blockIdx.x >> 5, n_t = blockIdx.x & 31;
    const int hc0  = kg*18;            // first half-chunk of this group

    // fragment-stream base pointers
    const uint4* Bb = d_Wb + (size_t)(n_t*4 + wn)*256 + lane;
    const uint4* A0 = d_Ha[0] + (size_t)(m_t*2 + wm)*4096 + lane;
    const uint4* A1 = d_Ha[1] + (size_t)(m_t*2 + wm)*4096 + lane;

    // epilogue ownership: thread -> row b0l, h-pairs hb, hb+1
    const int b0l = tid >> 4, hp = tid & 15;
    const int hl  = hp*2;                    // h within 32-slice (even)
    const int hg  = n_t*32 + hl;             // global h
    unsigned woff[2];
    {
        int hk = hg >> 5;
        int kk = hl & 15, ki = hl >> 4, chi = kk >> 3, qd = (kk & 7) >> 1;
        #pragma unroll
        for (int it = 0; it < 2; it++){
            int b = b0l + it*32;
            int rb = b >> 5, r32 = b & 31, mi = r32 >> 4, r16 = r32 & 15;
            int c = (r16 >> 3) + chi*2;
            int l = (r16 & 7)*4 + qd;
            int f = mi*2 + ki;
            woff[it] = (unsigned)(((((m_t*2+rb)*32 + hk)*4 + f)*32 + l)*4 + c);
        }
    }
    float Cst[2][2];
    #pragma unroll
    for (int it = 0; it < 2; it++){
        int b = m_t*64 + b0l + it*32;
        Cst[it][0] = C0[(size_t)b*HID + hg];
        Cst[it][1] = C0[(size_t)b*HID + hg + 1];
    }

    float acc[2][4][4];   // [mi][n8][c]
    uint4 av[2][4], bv[2][4];

    // pre-load first B half-chunk (weights are t-independent)
    {
        const uint4* bp = Bb + (size_t)(hc0>>1)*32768 + (hc0&1)*128;
        bv[0][0] = bp[0];  bv[0][1] = bp[32]; bv[0][2] = bp[64]; bv[0][3] = bp[96];
    }

    for (int t = 0; t < SEQ; ++t){
        const uint4* Ah = (t & 1) ? A1 : A0;
        unsigned* Hn = reinterpret_cast<unsigned*>((t & 1) ? d_Ha[0] : d_Ha[1]);
        const uint4* Xb = d_Xa + ((size_t)((t*4 + m_t)*2 + wm))*512 + lane;

        #pragma unroll
        for (int mi = 0; mi < 2; mi++)
            #pragma unroll
            for (int n8 = 0; n8 < 4; n8++)
                acc[mi][n8][0] = acc[mi][n8][1] = acc[mi][n8][2] = acc[mi][n8][3] = 0.0f;

        // first A half-chunk (depends on H -> after barrier); bv[0] already loaded
        {
            const uint4* ap = (hc0 < 32) ? (Ah + hc0*128) : (Xb + (hc0-32)*128);
            av[0][0] = ap[0];  av[0][1] = ap[32]; av[0][2] = ap[64]; av[0][3] = ap[96];
        }

        #pragma unroll 2
        for (int i = 0; i < 18; i++){
            int cb = i & 1, nb = cb ^ 1;
            int hn = hc0 + i + 1;
            if (i + 1 < 18){
                const uint4* ap = (hn < 32) ? (Ah + hn*128) : (Xb + (hn-32)*128);
                av[nb][0] = ap[0];  av[nb][1] = ap[32]; av[nb][2] = ap[64]; av[nb][3] = ap[96];
                const uint4* bp = Bb + (size_t)(hn>>1)*32768 + (hn&1)*128;
                bv[nb][0] = bp[0];  bv[nb][1] = bp[32]; bv[nb][2] = bp[64]; bv[nb][3] = bp[96];
            }
            #pragma unroll
            for (int ki = 0; ki < 2; ki++){
                uint4 b0 = bv[cb][ki*2], b1 = bv[cb][ki*2+1];
                #pragma unroll
                for (int mi = 0; mi < 2; mi++){
                    uint4 a = av[cb][mi*2 + ki];
                    mma16(acc[mi][0], a.x,a.y,a.z,a.w, b0.x, b0.y);
                    mma16(acc[mi][1], a.x,a.y,a.z,a.w, b0.z, b0.w);
                    mma16(acc[mi][2], a.x,a.y,a.z,a.w, b1.x, b1.y);
                    mma16(acc[mi][3], a.x,a.y,a.z,a.w, b1.z, b1.w);
                }
            }
        }

        // stage partial gates: gsm[kg][gate wn][row][h_l]
        {
            float* gb = gsm + kg*GKG + wn*GGT;
            #pragma unroll
            for (int mi = 0; mi < 2; mi++){
                int r0 = wm*32 + mi*16 + grp;
                #pragma unroll
                for (int n8 = 0; n8 < 4; n8++){
                    int nl = n8*8 + quad*2;
                    *reinterpret_cast<float2*>(&gb[r0*GST + nl])
                        = make_float2(acc[mi][n8][0], acc[mi][n8][1]);
                    *reinterpret_cast<float2*>(&gb[(r0+8)*GST + nl])
                        = make_float2(acc[mi][n8][2], acc[mi][n8][3]);
                }
            }
        }
        __syncthreads();

        // cell update: sum the two K-halves + bias; H into next step's frag image
        {
            float bi0 = d_biasp[hg],        bi1 = d_biasp[hg+1];
            float bf0 = d_biasp[1024+hg],   bf1 = d_biasp[1024+hg+1];
            float bo0 = d_biasp[2048+hg],   bo1 = d_biasp[2048+hg+1];
            float bc0 = d_biasp[3072+hg],   bc1 = d_biasp[3072+hg+1];
            #pragma unroll
            for (int it = 0; it < 2; it++){
                int b = b0l + it*32;
                float2 gi0 = *reinterpret_cast<float2*>(&gsm[        b*GST + hl]);
                float2 gf0 = *reinterpret_cast<float2*>(&gsm[GGT   + b*GST + hl]);
                float2 go0 = *reinterpret_cast<float2*>(&gsm[2*GGT + b*GST + hl]);
                float2 gc0 = *reinterpret_cast<float2*>(&gsm[3*GGT + b*GST + hl]);
                float2 gi1 = *reinterpret_cast<float2*>(&gsm[GKG         + b*GST + hl]);
                float2 gf1 = *reinterpret_cast<float2*>(&gsm[GKG + GGT   + b*GST + hl]);
                float2 go1 = *reinterpret_cast<float2*>(&gsm[GKG + 2*GGT + b*GST + hl]);
                float2 gc1 = *reinterpret_cast<float2*>(&gsm[GKG + 3*GGT + b*GST + hl]);
                float vi0 = gi0.x + gi1.x + bi0, vi1 = gi0.y + gi1.y + bi1;
                float vf0 = gf0.x + gf1.x + bf0, vf1 = gf0.y + gf1.y + bf1;
                float vo0 = go0.x + go1.x + bo0, vo1 = go0.y + go1.y + bo1;
                float vc0 = gc0.x + gc1.x + bc0, vc1 = gc0.y + gc1.y + bc1;
                float Cn0 = sigf(vf0)*Cst[it][0] + sigf(vi0)*tanhf(vc0);
                float Cn1 = sigf(vf1)*Cst[it][1] + sigf(vi1)*tanhf(vc1);
                Cst[it][0] = Cn0; Cst[it][1] = Cn1;
                float Hv0 = sigf(vo0)*tanhf(Cn0);
                float Hv1 = sigf(vo1)*tanhf(Cn1);
                Hn[woff[it]] = packh2(Hv0, Hv1);
            }
        }

        // prefetch next step's first B half-chunk (H-independent) before barrier
        if (t + 1 < SEQ){
            const uint4* bp = Bb + (size_t)(hc0>>1)*32768 + (hc0&1)*128;
            bv[0][0] = bp[0];  bv[0][1] = bp[32]; bv[0][2] = bp[64]; bv[0][3] = bp[96];
        }

        // grid barrier (per-m_t group of 32 CTAs; padded counters)
        __threadfence();
        __syncthreads();
        if (tid == 0){
            atomicAdd(&d_barc[m_t*32], 1u);
            unsigned target = (unsigned)(t+1)*32u, v;
            do { asm volatile("ld.acquire.gpu.u32 %0, [%1];" : "=r"(v) : "l"(&d_barc[m_t*32])); }
            while (v < target);
        }
        __syncthreads();
    }

    // ---- dense head: out[256,2] = H_final @ dense_w + dense_b (t=511 wrote buf 0) ----
    if (n_t == 0 && tid < 128){
        int rl = tid >> 1, cx = tid & 1;
        const unsigned* Hf = reinterpret_cast<const unsigned*>(d_Ha[0]);
        float sum = db[cx];
        int rb = rl >> 5, r32 = rl & 31, mi = r32 >> 4, r16 = r32 & 15;
        int clo = r16 >> 3, lbase = (r16 & 7)*4;
        for (int h = 0; h < HID; h += 2){
            int hk = h >> 5, h5 = h & 31, ki = h5 >> 4, kk = h5 & 15;
            int chi = kk >> 3, qd = (kk & 7) >> 1;
            int c = clo + chi*2, l = lbase + qd, f = mi*2 + ki;
            unsigned off = (unsigned)(((((m_t*2+rb)*32 + hk)*4 + f)*32 + l)*4 + c);
            unsigned v = Hf[off];
            __half2 hv = *reinterpret_cast<__half2*>(&v);
            sum += __low2float(hv)*dw[h*2 + cx] + __high2float(hv)*dw[(h+1)*2 + cx];
        }
        out[(m_t*64 + rl)*2 + cx] = sum;
    }
}

// ---------------- launcher ----------------
extern "C" void kernel_launch(void* const* d_in, const int* in_sizes, int n_in,
                              void* d_out, int out_size)
{
    const int*   tokens = (const int*)  d_in[0];
    const float* H0     = (const float*)d_in[1];
    const float* C0v    = (const float*)d_in[2];
    const float* Wxi = (const float*)d_in[3],  *Whi = (const float*)d_in[4],  *bi = (const float*)d_in[5];
    const float* Wxf = (const float*)d_in[6],  *Whf = (const float*)d_in[7],  *bf = (const float*)d_in[8];
    const float* Wxo = (const float*)d_in[9],  *Who = (const float*)d_in[10], *bo = (const float*)d_in[11];
    const float* Wxc = (const float*)d_in[12], *Whc = (const float*)d_in[13], *bc = (const float*)d_in[14];
    const float* emb = (const float*)d_in[15];
    const float* dw  = (const float*)d_in[16];
    const float* db  = (const float*)d_in[17];
    float* out = (float*)d_out;

    cudaFuncSetAttribute(lstm_dg, cudaFuncAttributeMaxDynamicSharedMemorySize, DSMEM);

    int total = NX + NW + NH + 4096;
    k_setup<<<(total + 255)/256, 256>>>(tokens, emb, H0,
        Wxi, Whi, Wxf, Whf, Wxo, Who, Wxc, Whc, bi, bf, bo, bc);
    // 128 CTAs (4 m-groups x 32 n-tiles), 512 threads, 1 CTA/SM
    lstm_dg<<<128, THREADS, DSMEM>>>(C0v, dw, db, out);
}